// round 13
// baseline (speedup 1.0000x reference)
#include <cuda_runtime.h>
#include <cuda_bf16.h>
#include <cstdint>

// Fused DepthwiseSeparableConv3d: depthwise 3x3x3 (SAME) + bias + BN + ReLU,
// then pointwise 64->128 GEMM + bias + BN + ReLU.
// B=2, D=H=W=48, C=64, F=128.
// R13: two-kernel scheme.
//  - prep kernel (1 block): folds BN1 scale into the depthwise weights,
//    folds BN2, converts pointwise weights to bf16 hi/lo in GEMM-fragment
//    layout ([f][c-pair] u32, 128B rows) in __device__ globals.
//  - main kernel: stage-1 threads compute BOTH h-rows via zh-row streaming
//    (96 x-LDG/thread instead of 153); GEMM B-fragments via __ldg from the
//    L1-resident prepped weights; smem = 27.6KB static (y tiles only);
//    __launch_bounds__(256,4) -> 4 CTAs/SM (32 warps) for latency hiding.

#define NB   2
#define ND   48
#define NC   64    // K
#define NF   128   // N
#define SW   144   // y-tile row stride in bytes (72 bf16)

#define OFF_YHI  0
#define OFF_YLO  (96 * SW)
#define SM_TOTAL (2 * 96 * SW)    // 27648 static

__device__ uint32_t g_wHi[NF * 32];   // [f][c-pair] bf16x2 of hi parts
__device__ uint32_t g_wLo[NF * 32];   // [f][c-pair] bf16x2 of lo parts
__device__ float    g_dwkS[27 * NC];  // dw kernel pre-multiplied by s1[c]
__device__ float    g_t1[NC];         // folded BN1 offset (incl. dw bias)
__device__ float    g_s2[NF];         // folded BN2 scale
__device__ float    g_t2[NF];         // folded BN2 offset (incl. pw bias)

__device__ __forceinline__ void mma_bf16(float* d, const uint32_t* a,
                                         const uint32_t* b) {
    asm volatile(
        "mma.sync.aligned.m16n8k16.row.col.f32.bf16.bf16.f32 "
        "{%0,%1,%2,%3}, {%4,%5,%6,%7}, {%8,%9}, {%0,%1,%2,%3};\n"
        : "+f"(d[0]), "+f"(d[1]), "+f"(d[2]), "+f"(d[3])
        : "r"(a[0]), "r"(a[1]), "r"(a[2]), "r"(a[3]), "r"(b[0]), "r"(b[1]));
}

__device__ __forceinline__ uint32_t bf16pair(float a, float b) {
    __nv_bfloat162 p = __floats2bfloat162_rn(a, b);
    return *(uint32_t*)&p;
}

// ---------------------------------------------------------------------------
__global__ void dwsep3d_prep(
    const float* __restrict__ dwk, const float* __restrict__ dwb,
    const float* __restrict__ g1, const float* __restrict__ b1,
    const float* __restrict__ m1, const float* __restrict__ v1,
    const float* __restrict__ pw, const float* __restrict__ pb,
    const float* __restrict__ g2, const float* __restrict__ b2,
    const float* __restrict__ m2, const float* __restrict__ v2)
{
    const int tid = threadIdx.x;
    if (tid < NC) {
        const int c = tid;
        const float inv = g1[c] * rsqrtf(v1[c] + 1e-3f);
        g_t1[c] = fmaf(dwb[c], inv, b1[c]) - m1[c] * inv;
        for (int t = 0; t < 27; t++)
            g_dwkS[t * NC + c] = dwk[t * NC + c] * inv;
    } else if (tid < NC + NF) {
        const int f = tid - NC;
        const float inv = g2[f] * rsqrtf(v2[f] + 1e-3f);
        g_s2[f] = inv;
        g_t2[f] = fmaf(pb[f], inv, b2[f]) - m2[f] * inv;
    }
    // weights: wT[f][c-pair] u32 of (bf16(c0), bf16(c1)), hi and lo parts
    for (int i = tid; i < 32 * NF; i += 256) {
        const int cp = i >> 7;             // 0..31
        const int f  = i & 127;
        const float w0v = pw[(2 * cp) * NF + f];
        const float w1v = pw[(2 * cp + 1) * NF + f];
        const __nv_bfloat16 h0v = __float2bfloat16(w0v);
        const __nv_bfloat16 h1v = __float2bfloat16(w1v);
        g_wHi[f * 32 + cp] =
            ((uint32_t)*(const uint16_t*)&h1v << 16) | *(const uint16_t*)&h0v;
        g_wLo[f * 32 + cp] = bf16pair(w0v - __bfloat162float(h0v),
                                      w1v - __bfloat162float(h1v));
    }
}

// ---------------------------------------------------------------------------
__global__ __launch_bounds__(256, 4)
void dwsep3d_mma_kernel(const float* __restrict__ x, float* __restrict__ out)
{
    __shared__ char smem[SM_TOTAL];

    const int tid = threadIdx.x;
    const int bid = blockIdx.x;            // 0 .. NB*ND*24-1
    const int h0 = (bid % 24) * 2;
    const int d  = (bid / 24) % ND;
    const int b  = bid / (24 * ND);

    // ---- stage 1: depthwise 3x3x3 (+folded BN1) + ReLU, both h-rows ---------
    // thread = (cp = tid&31 -> channels 2cp,2cp+1 ; ws = tid>>5 -> 6 w)
    {
        const int cp = tid & 31;
        const int c0 = cp * 2;
        const int ws = tid >> 5;           // 0..7 (warp-uniform)
        const int w0 = ws * 6;

        float2 acc[2][6];
        #pragma unroll
        for (int r = 0; r < 2; r++)
            #pragma unroll
            for (int j = 0; j < 6; j++) acc[r][j] = make_float2(0.f, 0.f);

        #pragma unroll
        for (int dd = 0; dd < 3; dd++) {
            const int zd = d + dd - 1;
            if (zd < 0 || zd >= ND) continue;
            // folded k for this dd: kk[hh][tap]
            float2 kk[3][3];
            #pragma unroll
            for (int hh = 0; hh < 3; hh++)
                #pragma unroll
                for (int t = 0; t < 3; t++)
                    kk[hh][t] = __ldg((const float2*)
                        &g_dwkS[((dd * 3 + hh) * 3 + t) * NC + c0]);

            #pragma unroll
            for (int zr = 0; zr < 4; zr++) {
                const int zh = h0 - 1 + zr;
                if (zh < 0 || zh >= ND) continue;   // block-uniform edges
                const float* xr =
                    x + (((size_t)((b * ND + zd) * ND + zh)) * ND) * NC + c0;
                float2 xv[8];   // taps w0-1 .. w0+6 (6 outputs)
                #pragma unroll
                for (int j = 1; j < 7; j++)
                    xv[j] = __ldg((const float2*)(xr + (w0 - 1 + j) * NC));
                xv[0] = (w0 > 0)
                    ? __ldg((const float2*)(xr + (w0 - 1) * NC))
                    : make_float2(0.f, 0.f);
                xv[7] = (w0 < 42)
                    ? __ldg((const float2*)(xr + (w0 + 6) * NC))
                    : make_float2(0.f, 0.f);

                if (zr < 3) {              // contributes to hr=0, hh = zr
                    #pragma unroll
                    for (int j = 0; j < 6; j++) {
                        acc[0][j].x = fmaf(xv[j].x, kk[zr][0].x,
                                      fmaf(xv[j+1].x, kk[zr][1].x,
                                       fmaf(xv[j+2].x, kk[zr][2].x, acc[0][j].x)));
                        acc[0][j].y = fmaf(xv[j].y, kk[zr][0].y,
                                      fmaf(xv[j+1].y, kk[zr][1].y,
                                       fmaf(xv[j+2].y, kk[zr][2].y, acc[0][j].y)));
                    }
                }
                if (zr >= 1) {             // contributes to hr=1, hh = zr-1
                    #pragma unroll
                    for (int j = 0; j < 6; j++) {
                        acc[1][j].x = fmaf(xv[j].x, kk[zr-1][0].x,
                                      fmaf(xv[j+1].x, kk[zr-1][1].x,
                                       fmaf(xv[j+2].x, kk[zr-1][2].x, acc[1][j].x)));
                        acc[1][j].y = fmaf(xv[j].y, kk[zr-1][0].y,
                                      fmaf(xv[j+1].y, kk[zr-1][1].y,
                                       fmaf(xv[j+2].y, kk[zr-1][2].y, acc[1][j].y)));
                    }
                }
            }
        }

        const float2 t1 = __ldg((const float2*)&g_t1[c0]);
        #pragma unroll
        for (int hr = 0; hr < 2; hr++) {
            #pragma unroll
            for (int j = 0; j < 6; j++) {
                const float z0 = fmaxf(acc[hr][j].x + t1.x, 0.f);
                const float z1 = fmaxf(acc[hr][j].y + t1.y, 0.f);
                const __nv_bfloat16 zh0 = __float2bfloat16(z0);
                const __nv_bfloat16 zh1 = __float2bfloat16(z1);
                const int m = hr * 48 + w0 + j;
                *(uint32_t*)(smem + OFF_YHI + m * SW + cp * 4) =
                    ((uint32_t)*(const uint16_t*)&zh1 << 16) |
                    *(const uint16_t*)&zh0;
                *(uint32_t*)(smem + OFF_YLO + m * SW + cp * 4) =
                    bf16pair(z0 - __bfloat162float(zh0),
                             z1 - __bfloat162float(zh1));
            }
        }
    }
    __syncthreads();

    // ---- stage 2: GEMM on tensor pipe, two m-half passes --------------------
    // warp w owns n16 = [w*16, w*16+16); B fragments via __ldg (L1-resident).
    {
        const int lane = tid & 31;
        const int wid  = tid >> 5;         // 0..7
        const int g    = lane >> 2;
        const int tg   = lane & 3;
        const int n0   = wid * 16;

        float* ob = out + (((size_t)((b * ND + d) * ND + h0)) * ND) * NF;

        #pragma unroll
        for (int mh = 0; mh < 2; mh++) {
            float acc[3][2][4];
            #pragma unroll
            for (int mt = 0; mt < 3; mt++)
                #pragma unroll
                for (int nt = 0; nt < 2; nt++)
                    #pragma unroll
                    for (int q = 0; q < 4; q++) acc[mt][nt][q] = 0.f;

            #pragma unroll
            for (int ks = 0; ks < 4; ks++) {
                const int kb  = ks * 32 + tg * 4;   // byte offset in y rows
                const int idx = ks * 8 + tg;        // u32 offset in w rows

                uint32_t bh[2][2], bl[2][2];
                #pragma unroll
                for (int nt = 0; nt < 2; nt++) {
                    const int nrow = n0 + nt * 8 + g;
                    bh[nt][0] = __ldg(&g_wHi[nrow * 32 + idx]);
                    bh[nt][1] = __ldg(&g_wHi[nrow * 32 + idx + 4]);
                    bl[nt][0] = __ldg(&g_wLo[nrow * 32 + idx]);
                    bl[nt][1] = __ldg(&g_wLo[nrow * 32 + idx + 4]);
                }

                #pragma unroll
                for (int mt = 0; mt < 3; mt++) {
                    const int mrow = (mh * 3 + mt) * 16 + g;
                    const char* ph = smem + OFF_YHI + mrow * SW + kb;
                    const char* pl = smem + OFF_YLO + mrow * SW + kb;
                    uint32_t ah[4], al[4];
                    ah[0] = *(const uint32_t*)ph;
                    ah[1] = *(const uint32_t*)(ph + 8 * SW);
                    ah[2] = *(const uint32_t*)(ph + 16);
                    ah[3] = *(const uint32_t*)(ph + 8 * SW + 16);
                    al[0] = *(const uint32_t*)pl;
                    al[1] = *(const uint32_t*)(pl + 8 * SW);
                    al[2] = *(const uint32_t*)(pl + 16);
                    al[3] = *(const uint32_t*)(pl + 8 * SW + 16);

                    #pragma unroll
                    for (int nt = 0; nt < 2; nt++) {
                        mma_bf16(acc[mt][nt], ah, bh[nt]);
                        mma_bf16(acc[mt][nt], ah, bl[nt]);
                        mma_bf16(acc[mt][nt], al, bh[nt]);
                    }
                }
            }

            // ---- epilogue for this m-half: BN2 + ReLU, float2 stores --------
            #pragma unroll
            for (int nt = 0; nt < 2; nt++) {
                const int f0 = n0 + nt * 8 + tg * 2;
                const float2 s2 = __ldg((const float2*)&g_s2[f0]);
                const float2 t2 = __ldg((const float2*)&g_t2[f0]);
                #pragma unroll
                for (int mt = 0; mt < 3; mt++) {
                    #pragma unroll
                    for (int half = 0; half < 2; half++) {
                        const int m = (mh * 3 + mt) * 16 + g + half * 8;
                        const int hr = (m >= 48) ? 1 : 0;
                        const int w  = m - hr * 48;
                        float2 o;
                        o.x = fmaxf(fmaf(acc[mt][nt][half * 2],     s2.x, t2.x), 0.f);
                        o.y = fmaxf(fmaf(acc[mt][nt][half * 2 + 1], s2.y, t2.y), 0.f);
                        *(float2*)&ob[((size_t)hr * ND + w) * NF + f0] = o;
                    }
                }
            }
        }
    }
}

extern "C" void kernel_launch(void* const* d_in, const int* in_sizes, int n_in,
                              void* d_out, int out_size) {
    const float* x   = (const float*)d_in[0];
    const float* dwk = (const float*)d_in[1];
    const float* dwb = (const float*)d_in[2];
    const float* g1  = (const float*)d_in[3];
    const float* b1  = (const float*)d_in[4];
    const float* m1  = (const float*)d_in[5];
    const float* v1  = (const float*)d_in[6];
    const float* pw  = (const float*)d_in[7];
    const float* pb  = (const float*)d_in[8];
    const float* g2  = (const float*)d_in[9];
    const float* b2  = (const float*)d_in[10];
    const float* m2  = (const float*)d_in[11];
    const float* v2  = (const float*)d_in[12];
    float* out = (float*)d_out;

    dwsep3d_prep<<<1, 256>>>(dwk, dwb, g1, b1, m1, v1,
                             pw, pb, g2, b2, m2, v2);
    dim3 grid(NB * ND * 24);   // 2304 blocks: one (b,d,h-pair) -> 96 voxels
    dwsep3d_mma_kernel<<<grid, 256>>>(x, out);
}

// round 15
// speedup vs baseline: 1.1382x; 1.1382x over previous
#include <cuda_runtime.h>
#include <cuda_bf16.h>
#include <cstdint>

// Fused DepthwiseSeparableConv3d: depthwise 3x3x3 (SAME) + bias + BN + ReLU,
// then pointwise 64->128 GEMM + bias + BN + ReLU.
// B=2, D=H=W=48, C=64, F=128.
// R15 = R14 resubmitted (R14 bench was an infra failure, not a kernel result):
//  (a) fully parallel prep kernel (48x128, one item/thread);
//  (b) GEMM A-fragments via ldmatrix.m8n8.x4 (1 LDSM replaces 8 LDS.32)
//      against R13's measured 83.9% L1tex roof.

#define NB   2
#define ND   48
#define NC   64    // K
#define NF   128   // N
#define SW   144   // y-tile row stride in bytes (72 bf16; 9*16B -> aligned)

#define OFF_YHI  0
#define OFF_YLO  (96 * SW)
#define SM_TOTAL (2 * 96 * SW)    // 27648 static

__device__ uint32_t g_wHi[NF * 32];   // [f][c-pair] bf16x2 of hi parts
__device__ uint32_t g_wLo[NF * 32];   // [f][c-pair] bf16x2 of lo parts
__device__ float    g_dwkS[27 * NC];  // dw kernel pre-multiplied by s1[c]
__device__ float    g_t1[NC];         // folded BN1 offset (incl. dw bias)
__device__ float    g_s2[NF];         // folded BN2 scale
__device__ float    g_t2[NF];         // folded BN2 offset (incl. pw bias)

__device__ __forceinline__ void mma_bf16(float* d, const uint32_t* a,
                                         const uint32_t* b) {
    asm volatile(
        "mma.sync.aligned.m16n8k16.row.col.f32.bf16.bf16.f32 "
        "{%0,%1,%2,%3}, {%4,%5,%6,%7}, {%8,%9}, {%0,%1,%2,%3};\n"
        : "+f"(d[0]), "+f"(d[1]), "+f"(d[2]), "+f"(d[3])
        : "r"(a[0]), "r"(a[1]), "r"(a[2]), "r"(a[3]), "r"(b[0]), "r"(b[1]));
}

__device__ __forceinline__ void ldsm_x4(uint32_t* r, uint32_t addr) {
    asm volatile(
        "ldmatrix.sync.aligned.m8n8.x4.shared.b16 {%0,%1,%2,%3}, [%4];"
        : "=r"(r[0]), "=r"(r[1]), "=r"(r[2]), "=r"(r[3]) : "r"(addr));
}

__device__ __forceinline__ uint32_t bf16pair(float a, float b) {
    __nv_bfloat162 p = __floats2bfloat162_rn(a, b);
    return *(uint32_t*)&p;
}

// ---------------------------------------------------------------------------
// prep: one work item per thread. grid 48 x 128 = 6144 threads.
//   [0, 4096)        : pointwise weight c-pair conversion
//   [4096, 5824)     : dwkS elements (27*64)
//   [5824, 5888)     : per-c BN1 fold
//   [5888, 6016)     : per-f BN2 fold
__global__ void dwsep3d_prep(
    const float* __restrict__ dwk, const float* __restrict__ dwb,
    const float* __restrict__ g1, const float* __restrict__ b1,
    const float* __restrict__ m1, const float* __restrict__ v1,
    const float* __restrict__ pw, const float* __restrict__ pb,
    const float* __restrict__ g2, const float* __restrict__ b2,
    const float* __restrict__ m2, const float* __restrict__ v2)
{
    const int t = blockIdx.x * 128 + threadIdx.x;
    if (t < 4096) {
        const int cp = t >> 7;             // 0..31
        const int f  = t & 127;
        const float w0v = pw[(2 * cp) * NF + f];
        const float w1v = pw[(2 * cp + 1) * NF + f];
        const __nv_bfloat16 h0v = __float2bfloat16(w0v);
        const __nv_bfloat16 h1v = __float2bfloat16(w1v);
        g_wHi[f * 32 + cp] =
            ((uint32_t)*(const uint16_t*)&h1v << 16) | *(const uint16_t*)&h0v;
        g_wLo[f * 32 + cp] = bf16pair(w0v - __bfloat162float(h0v),
                                      w1v - __bfloat162float(h1v));
    } else if (t < 5824) {
        const int e = t - 4096;
        const int c = e & 63;
        const float inv = g1[c] * rsqrtf(v1[c] + 1e-3f);
        g_dwkS[e] = dwk[e] * inv;
    } else if (t < 5888) {
        const int c = t - 5824;
        const float inv = g1[c] * rsqrtf(v1[c] + 1e-3f);
        g_t1[c] = fmaf(dwb[c], inv, b1[c]) - m1[c] * inv;
    } else if (t < 6016) {
        const int f = t - 5888;
        const float inv = g2[f] * rsqrtf(v2[f] + 1e-3f);
        g_s2[f] = inv;
        g_t2[f] = fmaf(pb[f], inv, b2[f]) - m2[f] * inv;
    }
}

// ---------------------------------------------------------------------------
__global__ __launch_bounds__(256, 4)
void dwsep3d_mma_kernel(const float* __restrict__ x, float* __restrict__ out)
{
    __shared__ char smem[SM_TOTAL];

    const int tid = threadIdx.x;
    const int bid = blockIdx.x;            // 0 .. NB*ND*24-1
    const int h0 = (bid % 24) * 2;
    const int d  = (bid / 24) % ND;
    const int b  = bid / (24 * ND);

    // ---- stage 1: depthwise 3x3x3 (+folded BN1) + ReLU, both h-rows ---------
    // thread = (cp = tid&31 -> channels 2cp,2cp+1 ; ws = tid>>5 -> 6 w)
    {
        const int cp = tid & 31;
        const int c0 = cp * 2;
        const int ws = tid >> 5;           // 0..7 (warp-uniform)
        const int w0 = ws * 6;

        float2 acc[2][6];
        #pragma unroll
        for (int r = 0; r < 2; r++)
            #pragma unroll
            for (int j = 0; j < 6; j++) acc[r][j] = make_float2(0.f, 0.f);

        #pragma unroll
        for (int dd = 0; dd < 3; dd++) {
            const int zd = d + dd - 1;
            if (zd < 0 || zd >= ND) continue;
            float2 kk[3][3];
            #pragma unroll
            for (int hh = 0; hh < 3; hh++)
                #pragma unroll
                for (int t = 0; t < 3; t++)
                    kk[hh][t] = __ldg((const float2*)
                        &g_dwkS[((dd * 3 + hh) * 3 + t) * NC + c0]);

            #pragma unroll
            for (int zr = 0; zr < 4; zr++) {
                const int zh = h0 - 1 + zr;
                if (zh < 0 || zh >= ND) continue;   // block-uniform edges
                const float* xr =
                    x + (((size_t)((b * ND + zd) * ND + zh)) * ND) * NC + c0;
                float2 xv[8];   // taps w0-1 .. w0+6 (6 outputs)
                #pragma unroll
                for (int j = 1; j < 7; j++)
                    xv[j] = __ldg((const float2*)(xr + (w0 - 1 + j) * NC));
                xv[0] = (w0 > 0)
                    ? __ldg((const float2*)(xr + (w0 - 1) * NC))
                    : make_float2(0.f, 0.f);
                xv[7] = (w0 < 42)
                    ? __ldg((const float2*)(xr + (w0 + 6) * NC))
                    : make_float2(0.f, 0.f);

                if (zr < 3) {              // hr=0, hh = zr
                    #pragma unroll
                    for (int j = 0; j < 6; j++) {
                        acc[0][j].x = fmaf(xv[j].x, kk[zr][0].x,
                                      fmaf(xv[j+1].x, kk[zr][1].x,
                                       fmaf(xv[j+2].x, kk[zr][2].x, acc[0][j].x)));
                        acc[0][j].y = fmaf(xv[j].y, kk[zr][0].y,
                                      fmaf(xv[j+1].y, kk[zr][1].y,
                                       fmaf(xv[j+2].y, kk[zr][2].y, acc[0][j].y)));
                    }
                }
                if (zr >= 1) {             // hr=1, hh = zr-1
                    #pragma unroll
                    for (int j = 0; j < 6; j++) {
                        acc[1][j].x = fmaf(xv[j].x, kk[zr-1][0].x,
                                      fmaf(xv[j+1].x, kk[zr-1][1].x,
                                       fmaf(xv[j+2].x, kk[zr-1][2].x, acc[1][j].x)));
                        acc[1][j].y = fmaf(xv[j].y, kk[zr-1][0].y,
                                      fmaf(xv[j+1].y, kk[zr-1][1].y,
                                       fmaf(xv[j+2].y, kk[zr-1][2].y, acc[1][j].y)));
                    }
                }
            }
        }

        const float2 t1 = __ldg((const float2*)&g_t1[c0]);
        #pragma unroll
        for (int hr = 0; hr < 2; hr++) {
            #pragma unroll
            for (int j = 0; j < 6; j++) {
                const float z0 = fmaxf(acc[hr][j].x + t1.x, 0.f);
                const float z1 = fmaxf(acc[hr][j].y + t1.y, 0.f);
                const __nv_bfloat16 zh0 = __float2bfloat16(z0);
                const __nv_bfloat16 zh1 = __float2bfloat16(z1);
                const int m = hr * 48 + w0 + j;
                *(uint32_t*)(smem + OFF_YHI + m * SW + cp * 4) =
                    ((uint32_t)*(const uint16_t*)&zh1 << 16) |
                    *(const uint16_t*)&zh0;
                *(uint32_t*)(smem + OFF_YLO + m * SW + cp * 4) =
                    bf16pair(z0 - __bfloat162float(zh0),
                             z1 - __bfloat162float(zh1));
            }
        }
    }
    __syncthreads();

    // ---- stage 2: GEMM on tensor pipe, two m-half passes --------------------
    // A-fragments via ldmatrix.x4; B-fragments via __ldg (L1-resident).
    {
        const int lane = tid & 31;
        const int wid  = tid >> 5;         // 0..7
        const int g    = lane >> 2;
        const int tg   = lane & 3;
        const int n0   = wid * 16;

        // ldmatrix per-lane address offset within a 16x16 tile:
        // mat = lane>>3 (0..3); row = (mat&1)*8 + lane&7 ; kbyte = (mat>>1)*16
        const int matid = lane >> 3;
        const uint32_t aoff =
            (uint32_t)(((matid & 1) * 8 + (lane & 7)) * SW + (matid >> 1) * 16);
        const uint32_t sbase = (uint32_t)__cvta_generic_to_shared(smem);

        float* ob = out + (((size_t)((b * ND + d) * ND + h0)) * ND) * NF;

        #pragma unroll
        for (int mh = 0; mh < 2; mh++) {
            float acc[3][2][4];
            #pragma unroll
            for (int mt = 0; mt < 3; mt++)
                #pragma unroll
                for (int nt = 0; nt < 2; nt++)
                    #pragma unroll
                    for (int q = 0; q < 4; q++) acc[mt][nt][q] = 0.f;

            #pragma unroll
            for (int ks = 0; ks < 4; ks++) {
                const int idx = ks * 8 + tg;        // u32 offset in w rows

                uint32_t bh[2][2], bl[2][2];
                #pragma unroll
                for (int nt = 0; nt < 2; nt++) {
                    const int nrow = n0 + nt * 8 + g;
                    bh[nt][0] = __ldg(&g_wHi[nrow * 32 + idx]);
                    bh[nt][1] = __ldg(&g_wHi[nrow * 32 + idx + 4]);
                    bl[nt][0] = __ldg(&g_wLo[nrow * 32 + idx]);
                    bl[nt][1] = __ldg(&g_wLo[nrow * 32 + idx + 4]);
                }

                #pragma unroll
                for (int mt = 0; mt < 3; mt++) {
                    const uint32_t tbase =
                        (uint32_t)((mh * 3 + mt) * 16 * SW + ks * 32) + aoff;
                    uint32_t ah[4], al[4];
                    ldsm_x4(ah, sbase + OFF_YHI + tbase);
                    ldsm_x4(al, sbase + OFF_YLO + tbase);

                    #pragma unroll
                    for (int nt = 0; nt < 2; nt++) {
                        mma_bf16(acc[mt][nt], ah, bh[nt]);
                        mma_bf16(acc[mt][nt], ah, bl[nt]);
                        mma_bf16(acc[mt][nt], al, bh[nt]);
                    }
                }
            }

            // ---- epilogue for this m-half: BN2 + ReLU, float2 stores --------
            #pragma unroll
            for (int nt = 0; nt < 2; nt++) {
                const int f0 = n0 + nt * 8 + tg * 2;
                const float2 s2 = __ldg((const float2*)&g_s2[f0]);
                const float2 t2 = __ldg((const float2*)&g_t2[f0]);
                #pragma unroll
                for (int mt = 0; mt < 3; mt++) {
                    #pragma unroll
                    for (int half = 0; half < 2; half++) {
                        const int m = (mh * 3 + mt) * 16 + g + half * 8;
                        const int hr = (m >= 48) ? 1 : 0;
                        const int w  = m - hr * 48;
                        float2 o;
                        o.x = fmaxf(fmaf(acc[mt][nt][half * 2],     s2.x, t2.x), 0.f);
                        o.y = fmaxf(fmaf(acc[mt][nt][half * 2 + 1], s2.y, t2.y), 0.f);
                        *(float2*)&ob[((size_t)hr * ND + w) * NF + f0] = o;
                    }
                }
            }
        }
    }
}

extern "C" void kernel_launch(void* const* d_in, const int* in_sizes, int n_in,
                              void* d_out, int out_size) {
    const float* x   = (const float*)d_in[0];
    const float* dwk = (const float*)d_in[1];
    const float* dwb = (const float*)d_in[2];
    const float* g1  = (const float*)d_in[3];
    const float* b1  = (const float*)d_in[4];
    const float* m1  = (const float*)d_in[5];
    const float* v1  = (const float*)d_in[6];
    const float* pw  = (const float*)d_in[7];
    const float* pb  = (const float*)d_in[8];
    const float* g2  = (const float*)d_in[9];
    const float* b2  = (const float*)d_in[10];
    const float* m2  = (const float*)d_in[11];
    const float* v2  = (const float*)d_in[12];
    float* out = (float*)d_out;

    dwsep3d_prep<<<48, 128>>>(dwk, dwb, g1, b1, m1, v1,
                              pw, pb, g2, b2, m2, v2);
    dim3 grid(NB * ND * 24);   // 2304 blocks: one (b,d,h-pair) -> 96 voxels
    dwsep3d_mma_kernel<<<grid, 256>>>(x, out);
}

// round 16
// speedup vs baseline: 1.3330x; 1.1712x over previous
#include <cuda_runtime.h>
#include <cuda_bf16.h>
#include <cstdint>

// Fused DepthwiseSeparableConv3d: depthwise 3x3x3 (SAME) + bias + BN + ReLU,
// then pointwise 64->128 GEMM + bias + BN + ReLU.
// B=2, D=H=W=48, C=64, F=128.
// R16 = R15 with the prepped pointwise weights re-laid-out into
// warp-contiguous fragment tiles: each warp B-fragment load now reads 32
// consecutive u32 (1 L1 wavefront) instead of scattering across 8 cache
// lines (8 wavefronts). Attacks the measured 84.2% L1tex roof.
// Layout: u32 for (f=nrow, cpair=ks*8+q*4+tg) lives at
//   [ ((ks*2+q)*16 + nrow/8) * 32 + (nrow%8)*4 + tg ]

#define NB   2
#define ND   48
#define NC   64    // K
#define NF   128   // N
#define SW   144   // y-tile row stride in bytes (72 bf16; 9*16B -> aligned)

#define OFF_YHI  0
#define OFF_YLO  (96 * SW)
#define SM_TOTAL (2 * 96 * SW)    // 27648 static

__device__ uint32_t g_wHi[4096];      // fragment-tiled hi parts (see header)
__device__ uint32_t g_wLo[4096];      // fragment-tiled lo parts
__device__ float    g_dwkS[27 * NC];  // dw kernel pre-multiplied by s1[c]
__device__ float    g_t1[NC];         // folded BN1 offset (incl. dw bias)
__device__ float    g_s2[NF];         // folded BN2 scale
__device__ float    g_t2[NF];         // folded BN2 offset (incl. pw bias)

__device__ __forceinline__ void mma_bf16(float* d, const uint32_t* a,
                                         const uint32_t* b) {
    asm volatile(
        "mma.sync.aligned.m16n8k16.row.col.f32.bf16.bf16.f32 "
        "{%0,%1,%2,%3}, {%4,%5,%6,%7}, {%8,%9}, {%0,%1,%2,%3};\n"
        : "+f"(d[0]), "+f"(d[1]), "+f"(d[2]), "+f"(d[3])
        : "r"(a[0]), "r"(a[1]), "r"(a[2]), "r"(a[3]), "r"(b[0]), "r"(b[1]));
}

__device__ __forceinline__ void ldsm_x4(uint32_t* r, uint32_t addr) {
    asm volatile(
        "ldmatrix.sync.aligned.m8n8.x4.shared.b16 {%0,%1,%2,%3}, [%4];"
        : "=r"(r[0]), "=r"(r[1]), "=r"(r[2]), "=r"(r[3]) : "r"(addr));
}

__device__ __forceinline__ uint32_t bf16pair(float a, float b) {
    __nv_bfloat162 p = __floats2bfloat162_rn(a, b);
    return *(uint32_t*)&p;
}

// ---------------------------------------------------------------------------
// prep: one work item per thread. grid 48 x 128 = 6144 threads.
__global__ void dwsep3d_prep(
    const float* __restrict__ dwk, const float* __restrict__ dwb,
    const float* __restrict__ g1, const float* __restrict__ b1,
    const float* __restrict__ m1, const float* __restrict__ v1,
    const float* __restrict__ pw, const float* __restrict__ pb,
    const float* __restrict__ g2, const float* __restrict__ b2,
    const float* __restrict__ m2, const float* __restrict__ v2)
{
    const int t = blockIdx.x * 128 + threadIdx.x;
    if (t < 4096) {
        const int cp = t >> 7;             // c-pair 0..31
        const int f  = t & 127;            // nrow 0..127
        const float w0v = pw[(2 * cp) * NF + f];
        const float w1v = pw[(2 * cp + 1) * NF + f];
        const __nv_bfloat16 h0v = __float2bfloat16(w0v);
        const __nv_bfloat16 h1v = __float2bfloat16(w1v);
        // fragment-tiled index
        const int ks  = cp >> 3;
        const int r   = cp & 7;
        const int q   = r >> 2;
        const int tg2 = r & 3;
        const int idx = (((ks * 2 + q) * 16 + (f >> 3)) * 8 + (f & 7)) * 4 + tg2;
        g_wHi[idx] =
            ((uint32_t)*(const uint16_t*)&h1v << 16) | *(const uint16_t*)&h0v;
        g_wLo[idx] = bf16pair(w0v - __bfloat162float(h0v),
                              w1v - __bfloat162float(h1v));
    } else if (t < 5824) {
        const int e = t - 4096;
        const int c = e & 63;
        const float inv = g1[c] * rsqrtf(v1[c] + 1e-3f);
        g_dwkS[e] = dwk[e] * inv;
    } else if (t < 5888) {
        const int c = t - 5824;
        const float inv = g1[c] * rsqrtf(v1[c] + 1e-3f);
        g_t1[c] = fmaf(dwb[c], inv, b1[c]) - m1[c] * inv;
    } else if (t < 6016) {
        const int f = t - 5888;
        const float inv = g2[f] * rsqrtf(v2[f] + 1e-3f);
        g_s2[f] = inv;
        g_t2[f] = fmaf(pb[f], inv, b2[f]) - m2[f] * inv;
    }
}

// ---------------------------------------------------------------------------
__global__ __launch_bounds__(256, 4)
void dwsep3d_mma_kernel(const float* __restrict__ x, float* __restrict__ out)
{
    __shared__ char smem[SM_TOTAL];

    const int tid = threadIdx.x;
    const int bid = blockIdx.x;            // 0 .. NB*ND*24-1
    const int h0 = (bid % 24) * 2;
    const int d  = (bid / 24) % ND;
    const int b  = bid / (24 * ND);

    // ---- stage 1: depthwise 3x3x3 (+folded BN1) + ReLU, both h-rows ---------
    {
        const int cp = tid & 31;
        const int c0 = cp * 2;
        const int ws = tid >> 5;           // 0..7 (warp-uniform)
        const int w0 = ws * 6;

        float2 acc[2][6];
        #pragma unroll
        for (int r = 0; r < 2; r++)
            #pragma unroll
            for (int j = 0; j < 6; j++) acc[r][j] = make_float2(0.f, 0.f);

        #pragma unroll
        for (int dd = 0; dd < 3; dd++) {
            const int zd = d + dd - 1;
            if (zd < 0 || zd >= ND) continue;
            float2 kk[3][3];
            #pragma unroll
            for (int hh = 0; hh < 3; hh++)
                #pragma unroll
                for (int t = 0; t < 3; t++)
                    kk[hh][t] = __ldg((const float2*)
                        &g_dwkS[((dd * 3 + hh) * 3 + t) * NC + c0]);

            #pragma unroll
            for (int zr = 0; zr < 4; zr++) {
                const int zh = h0 - 1 + zr;
                if (zh < 0 || zh >= ND) continue;   // block-uniform edges
                const float* xr =
                    x + (((size_t)((b * ND + zd) * ND + zh)) * ND) * NC + c0;
                float2 xv[8];   // taps w0-1 .. w0+6 (6 outputs)
                #pragma unroll
                for (int j = 1; j < 7; j++)
                    xv[j] = __ldg((const float2*)(xr + (w0 - 1 + j) * NC));
                xv[0] = (w0 > 0)
                    ? __ldg((const float2*)(xr + (w0 - 1) * NC))
                    : make_float2(0.f, 0.f);
                xv[7] = (w0 < 42)
                    ? __ldg((const float2*)(xr + (w0 + 6) * NC))
                    : make_float2(0.f, 0.f);

                if (zr < 3) {              // hr=0, hh = zr
                    #pragma unroll
                    for (int j = 0; j < 6; j++) {
                        acc[0][j].x = fmaf(xv[j].x, kk[zr][0].x,
                                      fmaf(xv[j+1].x, kk[zr][1].x,
                                       fmaf(xv[j+2].x, kk[zr][2].x, acc[0][j].x)));
                        acc[0][j].y = fmaf(xv[j].y, kk[zr][0].y,
                                      fmaf(xv[j+1].y, kk[zr][1].y,
                                       fmaf(xv[j+2].y, kk[zr][2].y, acc[0][j].y)));
                    }
                }
                if (zr >= 1) {             // hr=1, hh = zr-1
                    #pragma unroll
                    for (int j = 0; j < 6; j++) {
                        acc[1][j].x = fmaf(xv[j].x, kk[zr-1][0].x,
                                      fmaf(xv[j+1].x, kk[zr-1][1].x,
                                       fmaf(xv[j+2].x, kk[zr-1][2].x, acc[1][j].x)));
                        acc[1][j].y = fmaf(xv[j].y, kk[zr-1][0].y,
                                      fmaf(xv[j+1].y, kk[zr-1][1].y,
                                       fmaf(xv[j+2].y, kk[zr-1][2].y, acc[1][j].y)));
                    }
                }
            }
        }

        const float2 t1 = __ldg((const float2*)&g_t1[c0]);
        #pragma unroll
        for (int hr = 0; hr < 2; hr++) {
            #pragma unroll
            for (int j = 0; j < 6; j++) {
                const float z0 = fmaxf(acc[hr][j].x + t1.x, 0.f);
                const float z1 = fmaxf(acc[hr][j].y + t1.y, 0.f);
                const __nv_bfloat16 zh0 = __float2bfloat16(z0);
                const __nv_bfloat16 zh1 = __float2bfloat16(z1);
                const int m = hr * 48 + w0 + j;
                *(uint32_t*)(smem + OFF_YHI + m * SW + cp * 4) =
                    ((uint32_t)*(const uint16_t*)&zh1 << 16) |
                    *(const uint16_t*)&zh0;
                *(uint32_t*)(smem + OFF_YLO + m * SW + cp * 4) =
                    bf16pair(z0 - __bfloat162float(zh0),
                             z1 - __bfloat162float(zh1));
            }
        }
    }
    __syncthreads();

    // ---- stage 2: GEMM on tensor pipe, two m-half passes --------------------
    // A via ldmatrix.x4; B via warp-contiguous 1-wavefront __ldg tiles.
    {
        const int lane = tid & 31;
        const int wid  = tid >> 5;         // 0..7
        const int g    = lane >> 2;
        const int tg   = lane & 3;
        const int n0   = wid * 16;

        const int matid = lane >> 3;
        const uint32_t aoff =
            (uint32_t)(((matid & 1) * 8 + (lane & 7)) * SW + (matid >> 1) * 16);
        const uint32_t sbase = (uint32_t)__cvta_generic_to_shared(smem);

        float* ob = out + (((size_t)((b * ND + d) * ND + h0)) * ND) * NF;

        #pragma unroll
        for (int mh = 0; mh < 2; mh++) {
            float acc[3][2][4];
            #pragma unroll
            for (int mt = 0; mt < 3; mt++)
                #pragma unroll
                for (int nt = 0; nt < 2; nt++)
                    #pragma unroll
                    for (int q = 0; q < 4; q++) acc[mt][nt][q] = 0.f;

            #pragma unroll
            for (int ks = 0; ks < 4; ks++) {
                uint32_t bh[2][2], bl[2][2];
                #pragma unroll
                for (int nt = 0; nt < 2; nt++) {
                    // tile base for (ks, q, ngrp = wid*2+nt); lane adds g*4+tg
                    const int tb0 = ((ks * 2 + 0) * 16 + wid * 2 + nt) * 32 + lane;
                    const int tb1 = ((ks * 2 + 1) * 16 + wid * 2 + nt) * 32 + lane;
                    bh[nt][0] = __ldg(&g_wHi[tb0]);
                    bh[nt][1] = __ldg(&g_wHi[tb1]);
                    bl[nt][0] = __ldg(&g_wLo[tb0]);
                    bl[nt][1] = __ldg(&g_wLo[tb1]);
                }

                #pragma unroll
                for (int mt = 0; mt < 3; mt++) {
                    const uint32_t tbase =
                        (uint32_t)((mh * 3 + mt) * 16 * SW + ks * 32) + aoff;
                    uint32_t ah[4], al[4];
                    ldsm_x4(ah, sbase + OFF_YHI + tbase);
                    ldsm_x4(al, sbase + OFF_YLO + tbase);

                    #pragma unroll
                    for (int nt = 0; nt < 2; nt++) {
                        mma_bf16(acc[mt][nt], ah, bh[nt]);
                        mma_bf16(acc[mt][nt], ah, bl[nt]);
                        mma_bf16(acc[mt][nt], al, bh[nt]);
                    }
                }
            }

            // ---- epilogue for this m-half: BN2 + ReLU, float2 stores --------
            #pragma unroll
            for (int nt = 0; nt < 2; nt++) {
                const int f0 = n0 + nt * 8 + tg * 2;
                const float2 s2 = __ldg((const float2*)&g_s2[f0]);
                const float2 t2 = __ldg((const float2*)&g_t2[f0]);
                #pragma unroll
                for (int mt = 0; mt < 3; mt++) {
                    #pragma unroll
                    for (int half = 0; half < 2; half++) {
                        const int m = (mh * 3 + mt) * 16 + g + half * 8;
                        const int hr = (m >= 48) ? 1 : 0;
                        const int w  = m - hr * 48;
                        float2 o;
                        o.x = fmaxf(fmaf(acc[mt][nt][half * 2],     s2.x, t2.x), 0.f);
                        o.y = fmaxf(fmaf(acc[mt][nt][half * 2 + 1], s2.y, t2.y), 0.f);
                        *(float2*)&ob[((size_t)hr * ND + w) * NF + f0] = o;
                    }
                }
            }
        }
    }
}

extern "C" void kernel_launch(void* const* d_in, const int* in_sizes, int n_in,
                              void* d_out, int out_size) {
    const float* x   = (const float*)d_in[0];
    const float* dwk = (const float*)d_in[1];
    const float* dwb = (const float*)d_in[2];
    const float* g1  = (const float*)d_in[3];
    const float* b1  = (const float*)d_in[4];
    const float* m1  = (const float*)d_in[5];
    const float* v1  = (const float*)d_in[6];
    const float* pw  = (const float*)d_in[7];
    const float* pb  = (const float*)d_in[8];
    const float* g2  = (const float*)d_in[9];
    const float* b2  = (const float*)d_in[10];
    const float* m2  = (const float*)d_in[11];
    const float* v2  = (const float*)d_in[12];
    float* out = (float*)d_out;

    dwsep3d_prep<<<48, 128>>>(dwk, dwb, g1, b1, m1, v1,
                              pw, pb, g2, b2, m2, v2);
    dim3 grid(NB * ND * 24);   // 2304 blocks: one (b,d,h-pair) -> 96 voxels
    dwsep3d_mma_kernel<<<grid, 256>>>(x, out);
}